// round 9
// baseline (speedup 1.0000x reference)
#include <cuda_runtime.h>
#include <cstdint>

#define NN 2048
#define UU 64
#define RR 64

// ---- scratch (device globals; allocation is forbidden) ----
__device__ float g_E[(size_t)NN * NN];     // 16 MB: exp(score) matrix
__device__ float g_head[NN];
__device__ float g_tail[NN];
__device__ float g_colinv[NN];             // 1 / sum_i E[i,j]
__device__ float g_proped[NN * UU];        // softmax(S,axis=0) @ feature

// ---------------------------------------------------------------------------
// Kernel A: head[n] = relu(feature[n]·head_w + head_b), tail likewise
// ---------------------------------------------------------------------------
__global__ __launch_bounds__(256)
void head_tail_kernel(const float* __restrict__ feature,
                      const float* __restrict__ head_w,
                      const float* __restrict__ head_b,
                      const float* __restrict__ tail_w,
                      const float* __restrict__ tail_b) {
    int n = blockIdx.x * blockDim.x + threadIdx.x;
    if (n >= NN) return;
    const float4* f  = (const float4*)(feature + (size_t)n * UU);
    const float4* hw = (const float4*)head_w;
    const float4* tw = (const float4*)tail_w;
    float h = 0.f, t = 0.f;
#pragma unroll
    for (int k = 0; k < UU / 4; k++) {
        float4 v = f[k], a = hw[k], b = tw[k];
        h += v.x * a.x + v.y * a.y + v.z * a.z + v.w * a.w;
        t += v.x * b.x + v.y * b.y + v.z * b.z + v.w * b.w;
    }
    g_head[n] = fmaxf(h + head_b[0], 0.f);
    g_tail[n] = fmaxf(t + tail_b[0], 0.f);
}

// ---------------------------------------------------------------------------
// Kernel B (dominant, DRAM-bound): per pair p=(i,j)
//   E[p] = exp(rel_mask[p] + head[i] + tail[j] + relu(relation[p,:]·rel_w + rel_b))
// Exp is computed here (1 MUFU per 256B streamed — hidden under DRAM latency)
// so the two consumer kernels never touch MUFU.
// ---------------------------------------------------------------------------
__global__ __launch_bounds__(256)
void score_kernel(const float* __restrict__ relation,
                  const float* __restrict__ rel_mask,
                  const float* __restrict__ rel_w,
                  const float* __restrict__ rel_b,
                  float* __restrict__ E) {
    __shared__ float4 w4[16];
    int tid = threadIdx.x;
    if (tid < 16) w4[tid] = ((const float4*)rel_w)[tid];
    __syncthreads();

    int lane = tid & 15;
    int g    = tid >> 4;                 // 16 groups of 16 lanes
    size_t pb = (size_t)blockIdx.x * 64;
    float4 w = w4[lane];
    float rb = rel_b[0];

    const float4* rel4 = (const float4*)relation;

    // batch the 4 loads for MLP
    float4 r0 = rel4[(pb + 0 * 16 + g) * 16 + lane];
    float4 r1 = rel4[(pb + 1 * 16 + g) * 16 + lane];
    float4 r2 = rel4[(pb + 2 * 16 + g) * 16 + lane];
    float4 r3 = rel4[(pb + 3 * 16 + g) * 16 + lane];

#pragma unroll
    for (int k = 0; k < 4; k++) {
        float4 r = (k == 0) ? r0 : (k == 1) ? r1 : (k == 2) ? r2 : r3;
        float d = r.x * w.x + r.y * w.y + r.z * w.z + r.w * w.w;
#pragma unroll
        for (int o = 8; o; o >>= 1)
            d += __shfl_down_sync(0xffffffffu, d, o, 16);
        if (lane == 0) {
            size_t p = pb + (size_t)k * 16 + g;
            int i = (int)(p >> 11);
            int j = (int)(p & (NN - 1));
            float s = rel_mask[p] + g_head[i] + g_tail[j] + fmaxf(d + rb, 0.f);
            E[p] = __expf(s);            // masked (-1e9) underflows to 0
        }
    }
}

// ---------------------------------------------------------------------------
// Kernel C: colinv[j] = 1 / sum_i E[i,j]   (pure L2-resident sum, no exp)
// 32 cols x 8 row-threads per block; deterministic in-block reduction.
// ---------------------------------------------------------------------------
__global__ __launch_bounds__(256)
void colsum_kernel() {
    __shared__ float part[8][32];
    int c = threadIdx.x & 31;
    int r = threadIdx.x >> 5;
    int col = blockIdx.x * 32 + c;
    float s = 0.f;
#pragma unroll 4
    for (int row = r; row < NN; row += 8)
        s += g_E[(size_t)row * NN + col];
    part[r][c] = s;
    __syncthreads();
    if (r == 0) {
        float t = 0.f;
#pragma unroll
        for (int k = 0; k < 8; k++) t += part[k][c];
        g_colinv[col] = 1.0f / t;
    }
}

// ---------------------------------------------------------------------------
// Kernel D: proped = E @ (colinv ⊙ feature)   [2048x2048]@[2048x64]
// Block: 16 rows x 64 cols. Per-thread micro-tile 4i x 1u.
// E tile staged TRANSPOSED (Et[jj][ii], pad 20 keeps float4 alignment and
// limits store conflicts to 4-way); feature tile scaled by colinv at staging.
// Inner loop: 1 LDS.128 (warp-uniform broadcast) + 1 LDS.32 + 4 FFMA per jj.
// ---------------------------------------------------------------------------
__global__ __launch_bounds__(256)
void agg_kernel(const float* __restrict__ feature) {
    __shared__ float Et[128][20];       // 10 KB
    __shared__ float feat_s[128][UU];   // 32 KB
    int tid = threadIdx.x;              // 256
    int u  = tid & 63;
    int ig = tid >> 6;                  // 0..3 -> rows ig*4 .. ig*4+3
    int i0 = blockIdx.x * 16;

    float acc0 = 0.f, acc1 = 0.f, acc2 = 0.f, acc3 = 0.f;

    for (int j0 = 0; j0 < NN; j0 += 128) {
        __syncthreads();
        // stage E tile transposed: [16 rows][128 jj] -> Et[jj][ii]
#pragma unroll
        for (int k = 0; k < 8; k++) {
            int l = k * 256 + tid;
            int ii = l >> 7, jj = l & 127;
            Et[jj][ii] = g_E[(size_t)(i0 + ii) * NN + j0 + jj];
        }
        // stage colinv-scaled feature tile [128][64] (2048 float4 loads)
#pragma unroll
        for (int k = 0; k < 8; k++) {
            int l = k * 256 + tid;           // float4 index
            int jj = l >> 4, u4 = l & 15;
            float4 v = ((const float4*)(feature + (size_t)(j0 + jj) * UU))[u4];
            float cv = g_colinv[j0 + jj];
            v.x *= cv; v.y *= cv; v.z *= cv; v.w *= cv;
            ((float4*)&feat_s[jj][0])[u4] = v;
        }
        __syncthreads();
#pragma unroll 8
        for (int jj = 0; jj < 128; jj++) {
            float4 e = *(const float4*)&Et[jj][ig * 4];
            float f = feat_s[jj][u];
            acc0 += e.x * f; acc1 += e.y * f; acc2 += e.z * f; acc3 += e.w * f;
        }
    }
    g_proped[(size_t)(i0 + ig * 4 + 0) * UU + u] = acc0;
    g_proped[(size_t)(i0 + ig * 4 + 1) * UU + u] = acc1;
    g_proped[(size_t)(i0 + ig * 4 + 2) * UU + u] = acc2;
    g_proped[(size_t)(i0 + ig * 4 + 3) * UU + u] = acc3;
}

// ---------------------------------------------------------------------------
// Kernel E: prediction + losses, single block (256 thr x 8 rows),
// deterministic reduction.
// rank_loss = mean(relu(rr_i*rr_j*m_i*m_j)) = (P^2 + Ng^2)/N^2
//   with a_i = rr_i*m_i, P = sum(a_i>0), Ng = sum(a_i<0).
// ---------------------------------------------------------------------------
__global__ __launch_bounds__(256)
void loss_kernel(const float* __restrict__ feature,
                 const float* __restrict__ pred_w,
                 const float* __restrict__ pred_b,
                 const float* __restrict__ base_price,
                 const float* __restrict__ ground_truth,
                 const float* __restrict__ mask,
                 float* __restrict__ out, int out_size) {
    __shared__ float pw[2 * UU];
    __shared__ float s_sq[8], s_pos[8], s_neg[8];
    int tid = threadIdx.x;                // 256
    if (tid < 2 * UU) pw[tid] = pred_w[tid];
    __syncthreads();

    float pb = pred_b[0];
    float sq = 0.f, pos = 0.f, neg = 0.f;
    for (int k = 0; k < 8; k++) {
        int row = tid + k * 256;
        const float4* f = (const float4*)(feature + (size_t)row * UU);
        const float4* p = (const float4*)(g_proped + (size_t)row * UU);
        const float4* w0 = (const float4*)pw;
        const float4* w1 = (const float4*)(pw + UU);
        float d = 0.f;
#pragma unroll
        for (int r = 0; r < UU / 4; r++) {
            float4 v = f[r], w = w0[r];
            d += v.x * w.x + v.y * w.y + v.z * w.z + v.w * w.w;
        }
#pragma unroll
        for (int r = 0; r < UU / 4; r++) {
            float4 v = p[r], w = w1[r];
            d += v.x * w.x + v.y * w.y + v.z * w.z + v.w * w.w;
        }
        d += pb;
        float pred = (d >= 0.f) ? d : 0.2f * d;       // leaky_relu
        float bpv  = base_price[row];
        float rr   = (pred - bpv) / bpv;
        float diff = rr - ground_truth[row];
        sq += diff * diff;
        float a = rr * mask[row];
        pos += (a > 0.f) ? a : 0.f;
        neg += (a < 0.f) ? a : 0.f;
    }
#pragma unroll
    for (int o = 16; o; o >>= 1) {
        sq  += __shfl_down_sync(0xffffffffu, sq,  o);
        pos += __shfl_down_sync(0xffffffffu, pos, o);
        neg += __shfl_down_sync(0xffffffffu, neg, o);
    }
    if ((tid & 31) == 0) {
        s_sq[tid >> 5] = sq; s_pos[tid >> 5] = pos; s_neg[tid >> 5] = neg;
    }
    __syncthreads();
    if (tid == 0) {
        float tsq = 0.f, tp = 0.f, tn = 0.f;
#pragma unroll
        for (int k = 0; k < 8; k++) { tsq += s_sq[k]; tp += s_pos[k]; tn += s_neg[k]; }
        float reg  = tsq;
        float rank = (tp * tp + tn * tn) / ((float)NN * (float)NN);
        float loss = reg + 1.0f * rank;   // ALPHA = 1.0
        out[0] = loss;
        if (out_size > 1) out[1] = reg;
        if (out_size > 2) out[2] = rank;
    }
}

extern "C" void kernel_launch(void* const* d_in, const int* in_sizes, int n_in,
                              void* d_out, int out_size) {
    const float* feature      = (const float*)d_in[0];
    const float* relation     = (const float*)d_in[1];
    const float* rel_mask     = (const float*)d_in[2];
    const float* base_price   = (const float*)d_in[3];
    const float* ground_truth = (const float*)d_in[4];
    const float* mask         = (const float*)d_in[5];
    const float* rel_w        = (const float*)d_in[6];
    const float* rel_b        = (const float*)d_in[7];
    const float* head_w       = (const float*)d_in[8];
    const float* head_b       = (const float*)d_in[9];
    const float* tail_w       = (const float*)d_in[10];
    const float* tail_b       = (const float*)d_in[11];
    const float* pred_w       = (const float*)d_in[12];
    const float* pred_b       = (const float*)d_in[13];
    float* out = (float*)d_out;

    float* E;
    cudaGetSymbolAddress((void**)&E, g_E);

    head_tail_kernel<<<(NN + 255) / 256, 256>>>(feature, head_w, head_b, tail_w, tail_b);
    score_kernel<<<(size_t)NN * NN / 64, 256>>>(relation, rel_mask, rel_w, rel_b, E);
    colsum_kernel<<<NN / 32, 256>>>();
    agg_kernel<<<NN / 16, 256>>>(feature);
    loss_kernel<<<1, 256>>>(feature, pred_w, pred_b, base_price, ground_truth,
                            mask, out, out_size);
}

// round 11
// speedup vs baseline: 1.3612x; 1.3612x over previous
#include <cuda_runtime.h>
#include <cstdint>

#define NN 2048
#define UU 64
#define RR 64
#define JT 8                 // j-split tiles for agg
#define JC (NN / JT)         // 256 j per tile
#define KC 32                // j per smem stage

// ---- scratch (device globals; allocation is forbidden) ----
__device__ float g_E[(size_t)NN * NN];        // 16 MB: exp(score)
__device__ float g_head[NN];
__device__ float g_tail[NN];
__device__ float g_colinv[NN];                // 1 / sum_i E[i,j]
__device__ float g_part[JT][NN][UU];          // 4 MB agg partials
__device__ float g_proped[NN * UU];           // softmax(S,axis=0) @ feature

// ---------------------------------------------------------------------------
// Kernel A: head[n] = relu(feature[n]·head_w + head_b), tail likewise
// ---------------------------------------------------------------------------
__global__ __launch_bounds__(256)
void head_tail_kernel(const float* __restrict__ feature,
                      const float* __restrict__ head_w,
                      const float* __restrict__ head_b,
                      const float* __restrict__ tail_w,
                      const float* __restrict__ tail_b) {
    int n = blockIdx.x * blockDim.x + threadIdx.x;
    if (n >= NN) return;
    const float4* f  = (const float4*)(feature + (size_t)n * UU);
    const float4* hw = (const float4*)head_w;
    const float4* tw = (const float4*)tail_w;
    float h = 0.f, t = 0.f;
#pragma unroll
    for (int k = 0; k < UU / 4; k++) {
        float4 v = f[k], a = hw[k], b = tw[k];
        h += v.x * a.x + v.y * a.y + v.z * a.z + v.w * a.w;
        t += v.x * b.x + v.y * b.y + v.z * b.z + v.w * b.w;
    }
    g_head[n] = fmaxf(h + head_b[0], 0.f);
    g_tail[n] = fmaxf(t + tail_b[0], 0.f);
}

// ---------------------------------------------------------------------------
// Kernel B (dominant, DRAM-bound). Two phases per 64-pair block:
//  P1: 16 lanes/pair dot(relation[p,:], rel_w) -> smem ds[64]
//  P2: threads 0..63: s = rel_mask + head[i] + tail[j] + relu(d+rb);
//      E[p] = exp(s)  (exp spread over 2 warps; 256B coalesced store)
// ---------------------------------------------------------------------------
__global__ __launch_bounds__(256)
void score_kernel(const float* __restrict__ relation,
                  const float* __restrict__ rel_mask,
                  const float* __restrict__ rel_w,
                  const float* __restrict__ rel_b,
                  float* __restrict__ E) {
    __shared__ float4 w4[16];
    __shared__ float ds[64];
    int tid = threadIdx.x;
    if (tid < 16) w4[tid] = ((const float4*)rel_w)[tid];
    __syncthreads();

    int lane = tid & 15;
    int g    = tid >> 4;                 // 16 groups of 16 lanes
    size_t pb = (size_t)blockIdx.x * 64;
    float4 w = w4[lane];

    const float4* rel4 = (const float4*)relation;

    // batch the 4 pair-loads for MLP
    float4 r0 = rel4[(pb + 0 * 16 + g) * 16 + lane];
    float4 r1 = rel4[(pb + 1 * 16 + g) * 16 + lane];
    float4 r2 = rel4[(pb + 2 * 16 + g) * 16 + lane];
    float4 r3 = rel4[(pb + 3 * 16 + g) * 16 + lane];

#pragma unroll
    for (int k = 0; k < 4; k++) {
        float4 r = (k == 0) ? r0 : (k == 1) ? r1 : (k == 2) ? r2 : r3;
        float d = r.x * w.x + r.y * w.y + r.z * w.z + r.w * w.w;
#pragma unroll
        for (int o = 8; o; o >>= 1)
            d += __shfl_down_sync(0xffffffffu, d, o, 16);
        if (lane == 0) ds[k * 16 + g] = d;
    }
    __syncthreads();

    if (tid < 64) {
        size_t p = pb + tid;
        int i = (int)(p >> 11);
        int j = (int)(p & (NN - 1));
        float s = rel_mask[p] + g_head[i] + g_tail[j] +
                  fmaxf(ds[tid] + rel_b[0], 0.f);
        E[p] = __expf(s);                // masked (-1e9) underflows to 0
    }
}

// ---------------------------------------------------------------------------
// Kernel C: colinv[j] = 1 / sum_i E[i,j]   (pure L2-resident sum)
// 16 cols x 16 row-threads per block; 128 blocks; deterministic reduction.
// ---------------------------------------------------------------------------
__global__ __launch_bounds__(256)
void colsum_kernel() {
    __shared__ float part[16][16];
    int c = threadIdx.x & 15;
    int r = threadIdx.x >> 4;
    int col = blockIdx.x * 16 + c;
    float s = 0.f;
#pragma unroll 4
    for (int row = r; row < NN; row += 16)
        s += g_E[(size_t)row * NN + col];
    part[r][c] = s;
    __syncthreads();
    if (r == 0) {
        float t = 0.f;
#pragma unroll
        for (int k = 0; k < 16; k++) t += part[k][c];
        g_colinv[col] = 1.0f / t;
    }
}

// ---------------------------------------------------------------------------
// Kernel D: partial GEMM  part[jt] = E[:, jt-slice] @ (colinv ⊙ feature)[jt-slice]
// Grid 256 = 32 row-tiles (64 rows) x 8 j-tiles (256 j). 256 thr as 16x16,
// each thread a 4x4 micro-tile: per j-step 2 LDS.128 + 16 FFMA.
// ---------------------------------------------------------------------------
__global__ __launch_bounds__(256)
void agg_kernel(const float* __restrict__ feature) {
    __shared__ float Et[KC][68];      // E transposed [jj][row], pad 68 (4-way max)
    __shared__ float Fs[KC][UU];      // colinv-scaled feature [jj][u]
    int tid = threadIdx.x;
    int tx = tid & 15;                // u block: u = tx*4..tx*4+3
    int ty = tid >> 4;                // row block: r = ty*4..ty*4+3
    int i0 = (blockIdx.x & 31) * 64;
    int jt = blockIdx.x >> 5;         // 0..7
    int j0 = jt * JC;

    float acc[4][4] = {};

    for (int jc = 0; jc < JC; jc += KC) {
        __syncthreads();
        // stage Et: 64 rows x KC j, transposed (reads coalesced along j)
        {
            int j = tid & 31, rb = tid >> 5;
#pragma unroll
            for (int k = 0; k < 8; k++) {
                int r = rb + k * 8;
                Et[j][r] = g_E[(size_t)(i0 + r) * NN + j0 + jc + j];
            }
        }
        // stage Fs: KC j x 64 u, scaled by colinv (512 float4, 2 per thread)
        {
#pragma unroll
            for (int k = 0; k < 2; k++) {
                int l = k * 256 + tid;
                int j = l >> 4, u4 = l & 15;
                float4 v = ((const float4*)(feature + (size_t)(j0 + jc + j) * UU))[u4];
                float cv = g_colinv[j0 + jc + j];
                v.x *= cv; v.y *= cv; v.z *= cv; v.w *= cv;
                ((float4*)&Fs[j][0])[u4] = v;
            }
        }
        __syncthreads();
#pragma unroll 8
        for (int jj = 0; jj < KC; jj++) {
            float4 e = *(const float4*)&Et[jj][ty * 4];
            float4 f = *(const float4*)&Fs[jj][tx * 4];
            acc[0][0] += e.x * f.x; acc[0][1] += e.x * f.y;
            acc[0][2] += e.x * f.z; acc[0][3] += e.x * f.w;
            acc[1][0] += e.y * f.x; acc[1][1] += e.y * f.y;
            acc[1][2] += e.y * f.z; acc[1][3] += e.y * f.w;
            acc[2][0] += e.z * f.x; acc[2][1] += e.z * f.y;
            acc[2][2] += e.z * f.z; acc[2][3] += e.z * f.w;
            acc[3][0] += e.w * f.x; acc[3][1] += e.w * f.y;
            acc[3][2] += e.w * f.z; acc[3][3] += e.w * f.w;
        }
    }
#pragma unroll
    for (int r = 0; r < 4; r++) {
        float4 v = make_float4(acc[r][0], acc[r][1], acc[r][2], acc[r][3]);
        *(float4*)&g_part[jt][i0 + ty * 4 + r][tx * 4] = v;
    }
}

// ---------------------------------------------------------------------------
// Kernel D2: proped = sum_jt part[jt]   (fixed order -> deterministic)
// ---------------------------------------------------------------------------
__global__ __launch_bounds__(256)
void reduce_kernel() {
    int idx = blockIdx.x * 256 + threadIdx.x;     // over NN*UU/4 = 32768 float4
    const float4* p0 = (const float4*)&g_part[0][0][0];
    const size_t stride = (size_t)NN * UU / 4;
    float4 s = p0[idx];
#pragma unroll
    for (int jt = 1; jt < JT; jt++) {
        float4 v = p0[jt * stride + idx];
        s.x += v.x; s.y += v.y; s.z += v.z; s.w += v.w;
    }
    ((float4*)g_proped)[idx] = s;
}

// ---------------------------------------------------------------------------
// Kernel E: prediction + losses, single block (256 thr x 8 rows),
// deterministic reduction.
// rank_loss = mean(relu(rr_i*rr_j*m_i*m_j)) = (P^2 + Ng^2)/N^2
//   with a_i = rr_i*m_i, P = sum(a_i>0), Ng = sum(a_i<0).
// ---------------------------------------------------------------------------
__global__ __launch_bounds__(256)
void loss_kernel(const float* __restrict__ feature,
                 const float* __restrict__ pred_w,
                 const float* __restrict__ pred_b,
                 const float* __restrict__ base_price,
                 const float* __restrict__ ground_truth,
                 const float* __restrict__ mask,
                 float* __restrict__ out, int out_size) {
    __shared__ float pw[2 * UU];
    __shared__ float s_sq[8], s_pos[8], s_neg[8];
    int tid = threadIdx.x;                // 256
    if (tid < 2 * UU) pw[tid] = pred_w[tid];
    __syncthreads();

    float pb = pred_b[0];
    float sq = 0.f, pos = 0.f, neg = 0.f;
    for (int k = 0; k < 8; k++) {
        int row = tid + k * 256;
        const float4* f = (const float4*)(feature + (size_t)row * UU);
        const float4* p = (const float4*)(g_proped + (size_t)row * UU);
        const float4* w0 = (const float4*)pw;
        const float4* w1 = (const float4*)(pw + UU);
        float d = 0.f;
#pragma unroll
        for (int r = 0; r < UU / 4; r++) {
            float4 v = f[r], w = w0[r];
            d += v.x * w.x + v.y * w.y + v.z * w.z + v.w * w.w;
        }
#pragma unroll
        for (int r = 0; r < UU / 4; r++) {
            float4 v = p[r], w = w1[r];
            d += v.x * w.x + v.y * w.y + v.z * w.z + v.w * w.w;
        }
        d += pb;
        float pred = (d >= 0.f) ? d : 0.2f * d;       // leaky_relu
        float bpv  = base_price[row];
        float rr   = (pred - bpv) / bpv;
        float diff = rr - ground_truth[row];
        sq += diff * diff;
        float a = rr * mask[row];
        pos += (a > 0.f) ? a : 0.f;
        neg += (a < 0.f) ? a : 0.f;
    }
#pragma unroll
    for (int o = 16; o; o >>= 1) {
        sq  += __shfl_down_sync(0xffffffffu, sq,  o);
        pos += __shfl_down_sync(0xffffffffu, pos, o);
        neg += __shfl_down_sync(0xffffffffu, neg, o);
    }
    if ((tid & 31) == 0) {
        s_sq[tid >> 5] = sq; s_pos[tid >> 5] = pos; s_neg[tid >> 5] = neg;
    }
    __syncthreads();
    if (tid == 0) {
        float tsq = 0.f, tp = 0.f, tn = 0.f;
#pragma unroll
        for (int k = 0; k < 8; k++) { tsq += s_sq[k]; tp += s_pos[k]; tn += s_neg[k]; }
        float reg  = tsq;
        float rank = (tp * tp + tn * tn) / ((float)NN * (float)NN);
        float loss = reg + 1.0f * rank;   // ALPHA = 1.0
        out[0] = loss;
        if (out_size > 1) out[1] = reg;
        if (out_size > 2) out[2] = rank;
    }
}

extern "C" void kernel_launch(void* const* d_in, const int* in_sizes, int n_in,
                              void* d_out, int out_size) {
    const float* feature      = (const float*)d_in[0];
    const float* relation     = (const float*)d_in[1];
    const float* rel_mask     = (const float*)d_in[2];
    const float* base_price   = (const float*)d_in[3];
    const float* ground_truth = (const float*)d_in[4];
    const float* mask         = (const float*)d_in[5];
    const float* rel_w        = (const float*)d_in[6];
    const float* rel_b        = (const float*)d_in[7];
    const float* head_w       = (const float*)d_in[8];
    const float* head_b       = (const float*)d_in[9];
    const float* tail_w       = (const float*)d_in[10];
    const float* tail_b       = (const float*)d_in[11];
    const float* pred_w       = (const float*)d_in[12];
    const float* pred_b       = (const float*)d_in[13];
    float* out = (float*)d_out;

    float* E;
    cudaGetSymbolAddress((void**)&E, g_E);

    head_tail_kernel<<<(NN + 255) / 256, 256>>>(feature, head_w, head_b, tail_w, tail_b);
    score_kernel<<<(size_t)NN * NN / 64, 256>>>(relation, rel_mask, rel_w, rel_b, E);
    colsum_kernel<<<NN / 16, 256>>>();
    agg_kernel<<<32 * JT, 256>>>(feature);
    reduce_kernel<<<NN * UU / 4 / 256, 256>>>();
    loss_kernel<<<1, 256>>>(feature, pred_w, pred_b, base_price, ground_truth,
                            mask, out, out_size);
}

// round 13
// speedup vs baseline: 1.4108x; 1.0364x over previous
#include <cuda_runtime.h>
#include <cstdint>

#define NN 2048
#define UU 64
#define RR 64
#define JT 16                // j-split tiles for agg
#define JC (NN / JT)         // 128 j per tile
#define KC 32                // j per smem stage

// ---- scratch (device globals; allocation is forbidden) ----
__device__ float g_E[(size_t)NN * NN];        // 16 MB: exp(score)
__device__ float g_head[NN];
__device__ float g_tail[NN];
__device__ float g_colinv[NN];                // 1 / sum_i E[i,j]
__device__ float g_part[JT][NN][UU];          // 8 MB agg partials
__device__ float g_proped[NN * UU];           // softmax(S,axis=0) @ feature

// ---------------------------------------------------------------------------
// Kernel A: head[n] = relu(feature[n]·head_w + head_b), tail likewise
// ---------------------------------------------------------------------------
__global__ __launch_bounds__(256)
void head_tail_kernel(const float* __restrict__ feature,
                      const float* __restrict__ head_w,
                      const float* __restrict__ head_b,
                      const float* __restrict__ tail_w,
                      const float* __restrict__ tail_b) {
    int n = blockIdx.x * blockDim.x + threadIdx.x;
    if (n >= NN) return;
    const float4* f  = (const float4*)(feature + (size_t)n * UU);
    const float4* hw = (const float4*)head_w;
    const float4* tw = (const float4*)tail_w;
    float h = 0.f, t = 0.f;
#pragma unroll
    for (int k = 0; k < UU / 4; k++) {
        float4 v = f[k], a = hw[k], b = tw[k];
        h += v.x * a.x + v.y * a.y + v.z * a.z + v.w * a.w;
        t += v.x * b.x + v.y * b.y + v.z * b.z + v.w * b.w;
    }
    g_head[n] = fmaxf(h + head_b[0], 0.f);
    g_tail[n] = fmaxf(t + tail_b[0], 0.f);
}

// ---------------------------------------------------------------------------
// Kernel B (dominant, DRAM-bound). relation/rel_mask read with __ldcs
// (evict-first streaming) so the E matrix written here survives in L2 for
// colsum_kernel and agg_kernel.
//  P1: 16 lanes/pair dot(relation[p,:], rel_w) -> smem ds[64]
//  P2: threads 0..63: E[p] = exp(mask + head[i] + tail[j] + relu(d+rb))
// ---------------------------------------------------------------------------
__global__ __launch_bounds__(256)
void score_kernel(const float* __restrict__ relation,
                  const float* __restrict__ rel_mask,
                  const float* __restrict__ rel_w,
                  const float* __restrict__ rel_b,
                  float* __restrict__ E) {
    __shared__ float4 w4[16];
    __shared__ float ds[64];
    int tid = threadIdx.x;
    if (tid < 16) w4[tid] = ((const float4*)rel_w)[tid];
    __syncthreads();

    int lane = tid & 15;
    int g    = tid >> 4;                 // 16 groups of 16 lanes
    size_t pb = (size_t)blockIdx.x * 64;
    float4 w = w4[lane];

    const float4* rel4 = (const float4*)relation;

    // batch the 4 pair-loads for MLP (streaming: bypass-ish L2 residency)
    float4 r0 = __ldcs(&rel4[(pb + 0 * 16 + g) * 16 + lane]);
    float4 r1 = __ldcs(&rel4[(pb + 1 * 16 + g) * 16 + lane]);
    float4 r2 = __ldcs(&rel4[(pb + 2 * 16 + g) * 16 + lane]);
    float4 r3 = __ldcs(&rel4[(pb + 3 * 16 + g) * 16 + lane]);

#pragma unroll
    for (int k = 0; k < 4; k++) {
        float4 r = (k == 0) ? r0 : (k == 1) ? r1 : (k == 2) ? r2 : r3;
        float d = r.x * w.x + r.y * w.y + r.z * w.z + r.w * w.w;
#pragma unroll
        for (int o = 8; o; o >>= 1)
            d += __shfl_down_sync(0xffffffffu, d, o, 16);
        if (lane == 0) ds[k * 16 + g] = d;
    }
    __syncthreads();

    if (tid < 64) {
        size_t p = pb + tid;
        int i = (int)(p >> 11);
        int j = (int)(p & (NN - 1));
        float s = __ldcs(&rel_mask[p]) + g_head[i] + g_tail[j] +
                  fmaxf(ds[tid] + rel_b[0], 0.f);
        E[p] = __expf(s);                // masked (-1e9) underflows to 0
    }
}

// ---------------------------------------------------------------------------
// Kernel C: colinv[j] = 1 / sum_i E[i,j]   (L2-resident sum after ldcs fix)
// 16 cols x 16 row-threads per block; 128 blocks; deterministic reduction.
// ---------------------------------------------------------------------------
__global__ __launch_bounds__(256)
void colsum_kernel() {
    __shared__ float part[16][16];
    int c = threadIdx.x & 15;
    int r = threadIdx.x >> 4;
    int col = blockIdx.x * 16 + c;
    float s = 0.f;
#pragma unroll 4
    for (int row = r; row < NN; row += 16)
        s += g_E[(size_t)row * NN + col];
    part[r][c] = s;
    __syncthreads();
    if (r == 0) {
        float t = 0.f;
#pragma unroll
        for (int k = 0; k < 16; k++) t += part[k][c];
        g_colinv[col] = 1.0f / t;
    }
}

// ---------------------------------------------------------------------------
// Kernel D: partial GEMM  part[jt] = E[:, jt-slice] @ (colinv ⊙ feature)[jt-slice]
// Grid 256 = 16 row-tiles (128 rows) x 16 j-tiles (128 j each).
// 256 thr: tx = tid&7 (u = tx*8), ty = tid>>3 (rows ty*4..+3).
// Micro-tile 4x8: per j-step 3 LDS.128 + 32 FFMA -> FMA-pipe bound.
// ---------------------------------------------------------------------------
__global__ __launch_bounds__(256)
void agg_kernel(const float* __restrict__ feature) {
    __shared__ float Et[KC][132];     // E transposed [jj][row]; 132 keeps rows 16B-aligned
    __shared__ float Fs[KC][UU];      // colinv-scaled feature [jj][u]
    int tid = threadIdx.x;
    int tx = tid & 7;                 // u block: u = tx*8 .. +7
    int ty = tid >> 3;                // row block: r = ty*4 .. +3 (32 groups)
    int i0 = (blockIdx.x & 15) * 128;
    int jt = blockIdx.x >> 4;         // 0..15
    int j0 = jt * JC;

    float acc[4][8] = {};

    for (int jc = 0; jc < JC; jc += KC) {
        __syncthreads();
        // stage Et: 128 rows x KC j, transposed (global reads coalesced along j)
        {
            int j = tid & 31, rb = tid >> 5;
#pragma unroll
            for (int k = 0; k < 16; k++) {
                int r = rb + k * 8;
                Et[j][r] = g_E[(size_t)(i0 + r) * NN + j0 + jc + j];
            }
        }
        // stage Fs: KC j x 64 u, scaled by colinv (512 float4, 2 per thread)
        {
#pragma unroll
            for (int k = 0; k < 2; k++) {
                int l = k * 256 + tid;
                int j = l >> 4, u4 = l & 15;
                float4 v = ((const float4*)(feature + (size_t)(j0 + jc + j) * UU))[u4];
                float cv = g_colinv[j0 + jc + j];
                v.x *= cv; v.y *= cv; v.z *= cv; v.w *= cv;
                ((float4*)&Fs[j][0])[u4] = v;
            }
        }
        __syncthreads();
#pragma unroll 4
        for (int jj = 0; jj < KC; jj++) {
            float4 e  = *(const float4*)&Et[jj][ty * 4];
            float4 f0 = *(const float4*)&Fs[jj][tx * 8];
            float4 f1 = *(const float4*)&Fs[jj][tx * 8 + 4];
            acc[0][0] += e.x * f0.x; acc[0][1] += e.x * f0.y;
            acc[0][2] += e.x * f0.z; acc[0][3] += e.x * f0.w;
            acc[0][4] += e.x * f1.x; acc[0][5] += e.x * f1.y;
            acc[0][6] += e.x * f1.z; acc[0][7] += e.x * f1.w;
            acc[1][0] += e.y * f0.x; acc[1][1] += e.y * f0.y;
            acc[1][2] += e.y * f0.z; acc[1][3] += e.y * f0.w;
            acc[1][4] += e.y * f1.x; acc[1][5] += e.y * f1.y;
            acc[1][6] += e.y * f1.z; acc[1][7] += e.y * f1.w;
            acc[2][0] += e.z * f0.x; acc[2][1] += e.z * f0.y;
            acc[2][2] += e.z * f0.z; acc[2][3] += e.z * f0.w;
            acc[2][4] += e.z * f1.x; acc[2][5] += e.z * f1.y;
            acc[2][6] += e.z * f1.z; acc[2][7] += e.z * f1.w;
            acc[3][0] += e.w * f0.x; acc[3][1] += e.w * f0.y;
            acc[3][2] += e.w * f0.z; acc[3][3] += e.w * f0.w;
            acc[3][4] += e.w * f1.x; acc[3][5] += e.w * f1.y;
            acc[3][6] += e.w * f1.z; acc[3][7] += e.w * f1.w;
        }
    }
#pragma unroll
    for (int r = 0; r < 4; r++) {
        float* dst = &g_part[jt][i0 + ty * 4 + r][tx * 8];
        *(float4*)dst       = make_float4(acc[r][0], acc[r][1], acc[r][2], acc[r][3]);
        *(float4*)(dst + 4) = make_float4(acc[r][4], acc[r][5], acc[r][6], acc[r][7]);
    }
}

// ---------------------------------------------------------------------------
// Kernel D2: proped = sum_jt part[jt]   (fixed order -> deterministic)
// ---------------------------------------------------------------------------
__global__ __launch_bounds__(256)
void reduce_kernel() {
    int idx = blockIdx.x * 256 + threadIdx.x;     // over NN*UU/4 = 32768 float4
    const float4* p0 = (const float4*)&g_part[0][0][0];
    const size_t stride = (size_t)NN * UU / 4;
    float4 s = p0[idx];
#pragma unroll
    for (int jt = 1; jt < JT; jt++) {
        float4 v = p0[jt * stride + idx];
        s.x += v.x; s.y += v.y; s.z += v.z; s.w += v.w;
    }
    ((float4*)g_proped)[idx] = s;
}

// ---------------------------------------------------------------------------
// Kernel E: prediction + losses, single block (256 thr x 8 rows),
// deterministic reduction.
// rank_loss = mean(relu(rr_i*rr_j*m_i*m_j)) = (P^2 + Ng^2)/N^2
//   with a_i = rr_i*m_i, P = sum(a_i>0), Ng = sum(a_i<0).
// ---------------------------------------------------------------------------
__global__ __launch_bounds__(256)
void loss_kernel(const float* __restrict__ feature,
                 const float* __restrict__ pred_w,
                 const float* __restrict__ pred_b,
                 const float* __restrict__ base_price,
                 const float* __restrict__ ground_truth,
                 const float* __restrict__ mask,
                 float* __restrict__ out, int out_size) {
    __shared__ float pw[2 * UU];
    __shared__ float s_sq[8], s_pos[8], s_neg[8];
    int tid = threadIdx.x;                // 256
    if (tid < 2 * UU) pw[tid] = pred_w[tid];
    __syncthreads();

    float pb = pred_b[0];
    float sq = 0.f, pos = 0.f, neg = 0.f;
    for (int k = 0; k < 8; k++) {
        int row = tid + k * 256;
        const float4* f = (const float4*)(feature + (size_t)row * UU);
        const float4* p = (const float4*)(g_proped + (size_t)row * UU);
        const float4* w0 = (const float4*)pw;
        const float4* w1 = (const float4*)(pw + UU);
        float d = 0.f;
#pragma unroll
        for (int r = 0; r < UU / 4; r++) {
            float4 v = f[r], w = w0[r];
            d += v.x * w.x + v.y * w.y + v.z * w.z + v.w * w.w;
        }
#pragma unroll
        for (int r = 0; r < UU / 4; r++) {
            float4 v = p[r], w = w1[r];
            d += v.x * w.x + v.y * w.y + v.z * w.z + v.w * w.w;
        }
        d += pb;
        float pred = (d >= 0.f) ? d : 0.2f * d;       // leaky_relu
        float bpv  = base_price[row];
        float rr   = (pred - bpv) / bpv;
        float diff = rr - ground_truth[row];
        sq += diff * diff;
        float a = rr * mask[row];
        pos += (a > 0.f) ? a : 0.f;
        neg += (a < 0.f) ? a : 0.f;
    }
#pragma unroll
    for (int o = 16; o; o >>= 1) {
        sq  += __shfl_down_sync(0xffffffffu, sq,  o);
        pos += __shfl_down_sync(0xffffffffu, pos, o);
        neg += __shfl_down_sync(0xffffffffu, neg, o);
    }
    if ((tid & 31) == 0) {
        s_sq[tid >> 5] = sq; s_pos[tid >> 5] = pos; s_neg[tid >> 5] = neg;
    }
    __syncthreads();
    if (tid == 0) {
        float tsq = 0.f, tp = 0.f, tn = 0.f;
#pragma unroll
        for (int k = 0; k < 8; k++) { tsq += s_sq[k]; tp += s_pos[k]; tn += s_neg[k]; }
        float reg  = tsq;
        float rank = (tp * tp + tn * tn) / ((float)NN * (float)NN);
        float loss = reg + 1.0f * rank;   // ALPHA = 1.0
        out[0] = loss;
        if (out_size > 1) out[1] = reg;
        if (out_size > 2) out[2] = rank;
    }
}

extern "C" void kernel_launch(void* const* d_in, const int* in_sizes, int n_in,
                              void* d_out, int out_size) {
    const float* feature      = (const float*)d_in[0];
    const float* relation     = (const float*)d_in[1];
    const float* rel_mask     = (const float*)d_in[2];
    const float* base_price   = (const float*)d_in[3];
    const float* ground_truth = (const float*)d_in[4];
    const float* mask         = (const float*)d_in[5];
    const float* rel_w        = (const float*)d_in[6];
    const float* rel_b        = (const float*)d_in[7];
    const float* head_w       = (const float*)d_in[8];
    const float* head_b       = (const float*)d_in[9];
    const float* tail_w       = (const float*)d_in[10];
    const float* tail_b       = (const float*)d_in[11];
    const float* pred_w       = (const float*)d_in[12];
    const float* pred_b       = (const float*)d_in[13];
    float* out = (float*)d_out;

    float* E;
    cudaGetSymbolAddress((void**)&E, g_E);

    head_tail_kernel<<<(NN + 255) / 256, 256>>>(feature, head_w, head_b, tail_w, tail_b);
    score_kernel<<<(size_t)NN * NN / 64, 256>>>(relation, rel_mask, rel_w, rel_b, E);
    colsum_kernel<<<NN / 16, 256>>>();
    agg_kernel<<<16 * JT, 256>>>(feature);
    reduce_kernel<<<NN * UU / 4 / 256, 256>>>();
    loss_kernel<<<1, 256>>>(feature, pred_w, pred_b, base_price, ground_truth,
                            mask, out, out_size);
}

// round 14
// speedup vs baseline: 1.4455x; 1.0246x over previous
#include <cuda_runtime.h>
#include <cstdint>

#define NN 2048
#define UU 64
#define RR 64
#define JT 16                // j-split tiles for agg
#define JC (NN / JT)         // 128 j per tile
#define KC 32                // j per smem stage

// ---- scratch (device globals; allocation is forbidden) ----
__device__ float g_E[(size_t)NN * NN];        // 16 MB: exp(score)
__device__ float g_head[NN];
__device__ float g_tail[NN];
__device__ float g_colinv[NN];                // 1 / sum_i E[i,j]
__device__ float g_part[JT][NN][UU];          // 8 MB agg partials
__device__ float g_proped[NN * UU];           // softmax(S,axis=0) @ feature

// ---------------------------------------------------------------------------
// Kernel A: head[n] = relu(feature[n]·head_w + head_b), tail likewise
// ---------------------------------------------------------------------------
__global__ __launch_bounds__(256)
void head_tail_kernel(const float* __restrict__ feature,
                      const float* __restrict__ head_w,
                      const float* __restrict__ head_b,
                      const float* __restrict__ tail_w,
                      const float* __restrict__ tail_b) {
    int n = blockIdx.x * blockDim.x + threadIdx.x;
    if (n >= NN) return;
    const float4* f  = (const float4*)(feature + (size_t)n * UU);
    const float4* hw = (const float4*)head_w;
    const float4* tw = (const float4*)tail_w;
    float h = 0.f, t = 0.f;
#pragma unroll
    for (int k = 0; k < UU / 4; k++) {
        float4 v = f[k], a = hw[k], b = tw[k];
        h += v.x * a.x + v.y * a.y + v.z * a.z + v.w * a.w;
        t += v.x * b.x + v.y * b.y + v.z * b.z + v.w * b.w;
    }
    g_head[n] = fmaxf(h + head_b[0], 0.f);
    g_tail[n] = fmaxf(t + tail_b[0], 0.f);
}

// ---------------------------------------------------------------------------
// Kernel B (dominant, DRAM-bound). 128 pairs/block: 8 front-batched LDG.128
// per thread (MLP=8, 32KB contiguous per block). relation/rel_mask via __ldcs
// (evict-first) so E stays L2-resident for the consumers.
//  P1: 16 lanes/pair dot(relation[p,:], rel_w) -> smem ds[128]
//  P2: threads 0..127: E[p] = exp(mask + head[i] + tail[j] + relu(d+rb))
// ---------------------------------------------------------------------------
__global__ __launch_bounds__(256)
void score_kernel(const float* __restrict__ relation,
                  const float* __restrict__ rel_mask,
                  const float* __restrict__ rel_w,
                  const float* __restrict__ rel_b,
                  float* __restrict__ E) {
    __shared__ float4 w4[16];
    __shared__ float ds[128];
    int tid = threadIdx.x;
    if (tid < 16) w4[tid] = ((const float4*)rel_w)[tid];
    __syncthreads();

    int lane = tid & 15;
    int g    = tid >> 4;                 // 16 groups of 16 lanes
    size_t pb = (size_t)blockIdx.x * 128;
    float4 w = w4[lane];

    const float4* rel4 = (const float4*)relation;

    // 8 front-batched streaming loads (each k-chunk: 16 pairs, 4KB contiguous)
    float4 r[8];
#pragma unroll
    for (int k = 0; k < 8; k++)
        r[k] = __ldcs(&rel4[(pb + (size_t)k * 16 + g) * 16 + lane]);

#pragma unroll
    for (int k = 0; k < 8; k++) {
        float d = r[k].x * w.x + r[k].y * w.y + r[k].z * w.z + r[k].w * w.w;
#pragma unroll
        for (int o = 8; o; o >>= 1)
            d += __shfl_down_sync(0xffffffffu, d, o, 16);
        if (lane == 0) ds[k * 16 + g] = d;
    }
    __syncthreads();

    if (tid < 128) {
        size_t p = pb + tid;
        int i = (int)(p >> 11);
        int j = (int)(p & (NN - 1));
        float s = __ldcs(&rel_mask[p]) + g_head[i] + g_tail[j] +
                  fmaxf(ds[tid] + rel_b[0], 0.f);
        E[p] = __expf(s);                // masked (-1e9) underflows to 0
    }
}

// ---------------------------------------------------------------------------
// Kernel C: colinv[j] = 1 / sum_i E[i,j]   (L2-resident sum)
// 16 cols x 16 row-threads per block; 128 blocks; deterministic reduction.
// ---------------------------------------------------------------------------
__global__ __launch_bounds__(256)
void colsum_kernel() {
    __shared__ float part[16][16];
    int c = threadIdx.x & 15;
    int r = threadIdx.x >> 4;
    int col = blockIdx.x * 16 + c;
    float s = 0.f;
#pragma unroll 4
    for (int row = r; row < NN; row += 16)
        s += g_E[(size_t)row * NN + col];
    part[r][c] = s;
    __syncthreads();
    if (r == 0) {
        float t = 0.f;
#pragma unroll
        for (int k = 0; k < 16; k++) t += part[k][c];
        g_colinv[col] = 1.0f / t;
    }
}

// ---------------------------------------------------------------------------
// Kernel D: partial GEMM  part[jt] = E[:, jt-slice] @ (colinv ⊙ feature)[jt-slice]
// Grid 512 = 32 row-tiles (64 rows) x 16 j-tiles (128 j). 256 thr as 16x16,
// each thread a 4x4 micro-tile: per j-step 2 LDS.128 + 16 FFMA.
// ~3.5 blocks/SM -> occ ~40%, FMA-pipe bound.
// ---------------------------------------------------------------------------
__global__ __launch_bounds__(256)
void agg_kernel(const float* __restrict__ feature) {
    __shared__ float Et[KC][68];      // E transposed [jj][row], pad 68
    __shared__ float Fs[KC][UU];      // colinv-scaled feature [jj][u]
    int tid = threadIdx.x;
    int tx = tid & 15;                // u block: u = tx*4..tx*4+3
    int ty = tid >> 4;                // row block: r = ty*4..ty*4+3
    int i0 = (blockIdx.x & 31) * 64;
    int jt = blockIdx.x >> 5;         // 0..15
    int j0 = jt * JC;

    float acc[4][4] = {};

    for (int jc = 0; jc < JC; jc += KC) {
        __syncthreads();
        // stage Et: 64 rows x KC j, transposed (global reads coalesced along j)
        {
            int j = tid & 31, rb = tid >> 5;
#pragma unroll
            for (int k = 0; k < 8; k++) {
                int r = rb + k * 8;
                Et[j][r] = g_E[(size_t)(i0 + r) * NN + j0 + jc + j];
            }
        }
        // stage Fs: KC j x 64 u, scaled by colinv (512 float4, 2 per thread)
        {
#pragma unroll
            for (int k = 0; k < 2; k++) {
                int l = k * 256 + tid;
                int j = l >> 4, u4 = l & 15;
                float4 v = ((const float4*)(feature + (size_t)(j0 + jc + j) * UU))[u4];
                float cv = g_colinv[j0 + jc + j];
                v.x *= cv; v.y *= cv; v.z *= cv; v.w *= cv;
                ((float4*)&Fs[j][0])[u4] = v;
            }
        }
        __syncthreads();
#pragma unroll 8
        for (int jj = 0; jj < KC; jj++) {
            float4 e = *(const float4*)&Et[jj][ty * 4];
            float4 f = *(const float4*)&Fs[jj][tx * 4];
            acc[0][0] += e.x * f.x; acc[0][1] += e.x * f.y;
            acc[0][2] += e.x * f.z; acc[0][3] += e.x * f.w;
            acc[1][0] += e.y * f.x; acc[1][1] += e.y * f.y;
            acc[1][2] += e.y * f.z; acc[1][3] += e.y * f.w;
            acc[2][0] += e.z * f.x; acc[2][1] += e.z * f.y;
            acc[2][2] += e.z * f.z; acc[2][3] += e.z * f.w;
            acc[3][0] += e.w * f.x; acc[3][1] += e.w * f.y;
            acc[3][2] += e.w * f.z; acc[3][3] += e.w * f.w;
        }
    }
#pragma unroll
    for (int r = 0; r < 4; r++) {
        float4 v = make_float4(acc[r][0], acc[r][1], acc[r][2], acc[r][3]);
        *(float4*)&g_part[jt][i0 + ty * 4 + r][tx * 4] = v;
    }
}

// ---------------------------------------------------------------------------
// Kernel D2: proped = sum_jt part[jt]   (fixed order -> deterministic)
// ---------------------------------------------------------------------------
__global__ __launch_bounds__(256)
void reduce_kernel() {
    int idx = blockIdx.x * 256 + threadIdx.x;     // over NN*UU/4 = 32768 float4
    const float4* p0 = (const float4*)&g_part[0][0][0];
    const size_t stride = (size_t)NN * UU / 4;
    float4 s = p0[idx];
#pragma unroll
    for (int jt = 1; jt < JT; jt++) {
        float4 v = p0[jt * stride + idx];
        s.x += v.x; s.y += v.y; s.z += v.z; s.w += v.w;
    }
    ((float4*)g_proped)[idx] = s;
}

// ---------------------------------------------------------------------------
// Kernel E: prediction + losses, single block (256 thr x 8 rows),
// deterministic reduction.
// rank_loss = mean(relu(rr_i*rr_j*m_i*m_j)) = (P^2 + Ng^2)/N^2
//   with a_i = rr_i*m_i, P = sum(a_i>0), Ng = sum(a_i<0).
// ---------------------------------------------------------------------------
__global__ __launch_bounds__(256)
void loss_kernel(const float* __restrict__ feature,
                 const float* __restrict__ pred_w,
                 const float* __restrict__ pred_b,
                 const float* __restrict__ base_price,
                 const float* __restrict__ ground_truth,
                 const float* __restrict__ mask,
                 float* __restrict__ out, int out_size) {
    __shared__ float pw[2 * UU];
    __shared__ float s_sq[8], s_pos[8], s_neg[8];
    int tid = threadIdx.x;                // 256
    if (tid < 2 * UU) pw[tid] = pred_w[tid];
    __syncthreads();

    float pb = pred_b[0];
    float sq = 0.f, pos = 0.f, neg = 0.f;
    for (int k = 0; k < 8; k++) {
        int row = tid + k * 256;
        const float4* f = (const float4*)(feature + (size_t)row * UU);
        const float4* p = (const float4*)(g_proped + (size_t)row * UU);
        const float4* w0 = (const float4*)pw;
        const float4* w1 = (const float4*)(pw + UU);
        float d = 0.f;
#pragma unroll
        for (int r = 0; r < UU / 4; r++) {
            float4 v = f[r], w = w0[r];
            d += v.x * w.x + v.y * w.y + v.z * w.z + v.w * w.w;
        }
#pragma unroll
        for (int r = 0; r < UU / 4; r++) {
            float4 v = p[r], w = w1[r];
            d += v.x * w.x + v.y * w.y + v.z * w.z + v.w * w.w;
        }
        d += pb;
        float pred = (d >= 0.f) ? d : 0.2f * d;       // leaky_relu
        float bpv  = base_price[row];
        float rr   = (pred - bpv) / bpv;
        float diff = rr - ground_truth[row];
        sq += diff * diff;
        float a = rr * mask[row];
        pos += (a > 0.f) ? a : 0.f;
        neg += (a < 0.f) ? a : 0.f;
    }
#pragma unroll
    for (int o = 16; o; o >>= 1) {
        sq  += __shfl_down_sync(0xffffffffu, sq,  o);
        pos += __shfl_down_sync(0xffffffffu, pos, o);
        neg += __shfl_down_sync(0xffffffffu, neg, o);
    }
    if ((tid & 31) == 0) {
        s_sq[tid >> 5] = sq; s_pos[tid >> 5] = pos; s_neg[tid >> 5] = neg;
    }
    __syncthreads();
    if (tid == 0) {
        float tsq = 0.f, tp = 0.f, tn = 0.f;
#pragma unroll
        for (int k = 0; k < 8; k++) { tsq += s_sq[k]; tp += s_pos[k]; tn += s_neg[k]; }
        float reg  = tsq;
        float rank = (tp * tp + tn * tn) / ((float)NN * (float)NN);
        float loss = reg + 1.0f * rank;   // ALPHA = 1.0
        out[0] = loss;
        if (out_size > 1) out[1] = reg;
        if (out_size > 2) out[2] = rank;
    }
}

extern "C" void kernel_launch(void* const* d_in, const int* in_sizes, int n_in,
                              void* d_out, int out_size) {
    const float* feature      = (const float*)d_in[0];
    const float* relation     = (const float*)d_in[1];
    const float* rel_mask     = (const float*)d_in[2];
    const float* base_price   = (const float*)d_in[3];
    const float* ground_truth = (const float*)d_in[4];
    const float* mask         = (const float*)d_in[5];
    const float* rel_w        = (const float*)d_in[6];
    const float* rel_b        = (const float*)d_in[7];
    const float* head_w       = (const float*)d_in[8];
    const float* head_b       = (const float*)d_in[9];
    const float* tail_w       = (const float*)d_in[10];
    const float* tail_b       = (const float*)d_in[11];
    const float* pred_w       = (const float*)d_in[12];
    const float* pred_b       = (const float*)d_in[13];
    float* out = (float*)d_out;

    float* E;
    cudaGetSymbolAddress((void**)&E, g_E);

    head_tail_kernel<<<(NN + 255) / 256, 256>>>(feature, head_w, head_b, tail_w, tail_b);
    score_kernel<<<(size_t)NN * NN / 128, 256>>>(relation, rel_mask, rel_w, rel_b, E);
    colsum_kernel<<<NN / 16, 256>>>();
    agg_kernel<<<32 * JT, 256>>>(feature);
    reduce_kernel<<<NN * UU / 4 / 256, 256>>>();
    loss_kernel<<<1, 256>>>(feature, pred_w, pred_b, base_price, ground_truth,
                            mask, out, out_size);
}

// round 16
// speedup vs baseline: 1.4778x; 1.0224x over previous
#include <cuda_runtime.h>
#include <cstdint>

#define NN 2048
#define UU 64
#define RR 64
#define JT 32                // j-split tiles for agg
#define JC (NN / JT)         // 64 j per tile
#define KC 32                // j per smem stage
#define CS 64                // colsum partial slices

// ---- scratch (device globals; allocation is forbidden) ----
__device__ float g_E[(size_t)NN * NN];        // 16 MB: exp(score)
__device__ float g_head[NN];
__device__ float g_tail[NN];
__device__ float g_colpart[CS][NN];           // 512 KB colsum partials
__device__ float g_colinv[NN];                // 1 / sum_i E[i,j]
__device__ float g_part[JT][NN][UU];          // 16 MB agg partials
__device__ float g_proped[NN * UU];           // softmax(S,axis=0) @ feature

// ---------------------------------------------------------------------------
// Kernel A: head[n] = relu(feature[n]·head_w + head_b), tail likewise
// ---------------------------------------------------------------------------
__global__ __launch_bounds__(256)
void head_tail_kernel(const float* __restrict__ feature,
                      const float* __restrict__ head_w,
                      const float* __restrict__ head_b,
                      const float* __restrict__ tail_w,
                      const float* __restrict__ tail_b) {
    int n = blockIdx.x * blockDim.x + threadIdx.x;
    if (n >= NN) return;
    const float4* f  = (const float4*)(feature + (size_t)n * UU);
    const float4* hw = (const float4*)head_w;
    const float4* tw = (const float4*)tail_w;
    float h = 0.f, t = 0.f;
#pragma unroll
    for (int k = 0; k < UU / 4; k++) {
        float4 v = f[k], a = hw[k], b = tw[k];
        h += v.x * a.x + v.y * a.y + v.z * a.z + v.w * a.w;
        t += v.x * b.x + v.y * b.y + v.z * b.z + v.w * b.w;
    }
    g_head[n] = fmaxf(h + head_b[0], 0.f);
    g_tail[n] = fmaxf(t + tail_b[0], 0.f);
}

// ---------------------------------------------------------------------------
// Kernel B (dominant, DRAM-bound). 128 pairs/block: 8 front-batched LDG.128
// per thread (MLP=8, 32KB contiguous per block). relation/rel_mask via __ldcs
// (evict-first) so E stays L2-resident for the consumers.
// ---------------------------------------------------------------------------
__global__ __launch_bounds__(256)
void score_kernel(const float* __restrict__ relation,
                  const float* __restrict__ rel_mask,
                  const float* __restrict__ rel_w,
                  const float* __restrict__ rel_b,
                  float* __restrict__ E) {
    __shared__ float4 w4[16];
    __shared__ float ds[128];
    int tid = threadIdx.x;
    if (tid < 16) w4[tid] = ((const float4*)rel_w)[tid];
    __syncthreads();

    int lane = tid & 15;
    int g    = tid >> 4;                 // 16 groups of 16 lanes
    size_t pb = (size_t)blockIdx.x * 128;
    float4 w = w4[lane];

    const float4* rel4 = (const float4*)relation;

    float4 r[8];
#pragma unroll
    for (int k = 0; k < 8; k++)
        r[k] = __ldcs(&rel4[(pb + (size_t)k * 16 + g) * 16 + lane]);

#pragma unroll
    for (int k = 0; k < 8; k++) {
        float d = r[k].x * w.x + r[k].y * w.y + r[k].z * w.z + r[k].w * w.w;
#pragma unroll
        for (int o = 8; o; o >>= 1)
            d += __shfl_down_sync(0xffffffffu, d, o, 16);
        if (lane == 0) ds[k * 16 + g] = d;
    }
    __syncthreads();

    if (tid < 128) {
        size_t p = pb + tid;
        int i = (int)(p >> 11);
        int j = (int)(p & (NN - 1));
        float s = __ldcs(&rel_mask[p]) + g_head[i] + g_tail[j] +
                  fmaxf(ds[tid] + rel_b[0], 0.f);
        E[p] = __expf(s);                // masked (-1e9) underflows to 0
    }
}

// ---------------------------------------------------------------------------
// Kernel C1: row-coalesced partial column sums of E.
// Grid 128 = 4 col-tiles (512 cols) x 32 row-tiles (64 rows).
// Thread owns a float4 of columns; accumulates 32 rows with 4-way MLP.
// ---------------------------------------------------------------------------
__global__ __launch_bounds__(256)
void colsum1_kernel() {
    int tid = threadIdx.x;
    int cb = blockIdx.x & 3;          // col tile
    int rb = blockIdx.x >> 2;         // row tile 0..31
    int c4 = tid & 127;
    int rt = tid >> 7;                // 0..1
    int col = cb * 512 + c4 * 4;
    const float4* E4 = (const float4*)g_E;
    float4 a0 = make_float4(0, 0, 0, 0), a1 = a0, a2 = a0, a3 = a0;
    int base = rb * 64 + rt;
#pragma unroll 4
    for (int it = 0; it < 32; it += 4) {
        float4 v0 = E4[((size_t)(base + 2 * (it + 0)) * NN + col) >> 2];
        float4 v1 = E4[((size_t)(base + 2 * (it + 1)) * NN + col) >> 2];
        float4 v2 = E4[((size_t)(base + 2 * (it + 2)) * NN + col) >> 2];
        float4 v3 = E4[((size_t)(base + 2 * (it + 3)) * NN + col) >> 2];
        a0.x += v0.x; a0.y += v0.y; a0.z += v0.z; a0.w += v0.w;
        a1.x += v1.x; a1.y += v1.y; a1.z += v1.z; a1.w += v1.w;
        a2.x += v2.x; a2.y += v2.y; a2.z += v2.z; a2.w += v2.w;
        a3.x += v3.x; a3.y += v3.y; a3.z += v3.z; a3.w += v3.w;
    }
    float4 s = make_float4(a0.x + a1.x + a2.x + a3.x,
                           a0.y + a1.y + a2.y + a3.y,
                           a0.z + a1.z + a2.z + a3.z,
                           a0.w + a1.w + a2.w + a3.w);
    *(float4*)&g_colpart[rb * 2 + rt][col] = s;
}

// ---------------------------------------------------------------------------
// Kernel C2: colinv[j] = 1 / sum_k colpart[k][j]  (fixed order, coalesced)
// ---------------------------------------------------------------------------
__global__ __launch_bounds__(256)
void colsum2_kernel() {
    int j = blockIdx.x * 256 + threadIdx.x;   // 2048
    float s = 0.f;
#pragma unroll
    for (int k = 0; k < CS; k++) s += g_colpart[k][j];
    g_colinv[j] = 1.0f / s;
}

// ---------------------------------------------------------------------------
// Kernel D: partial GEMM  part[jt] = E[:, jt-slice] @ (colinv ⊙ feature)[jt-slice]
// Grid 1024 = 32 row-tiles (64 rows) x 32 j-tiles (64 j). 256 thr as 16x16,
// each thread a 4x4 micro-tile: 2 LDS.128 + 16 FFMA per j-step.
// 5 blocks/SM (reg cap) -> occ 62.5%.
// ---------------------------------------------------------------------------
__global__ __launch_bounds__(256)
void agg_kernel(const float* __restrict__ feature) {
    __shared__ float Et[KC][68];      // E transposed [jj][row], pad 68
    __shared__ float Fs[KC][UU];      // colinv-scaled feature [jj][u]
    int tid = threadIdx.x;
    int tx = tid & 15;                // u block: u = tx*4..tx*4+3
    int ty = tid >> 4;                // row block: r = ty*4..ty*4+3
    int i0 = (blockIdx.x & 31) * 64;
    int jt = blockIdx.x >> 5;         // 0..31
    int j0 = jt * JC;

    float acc[4][4] = {};

#pragma unroll
    for (int jc = 0; jc < JC; jc += KC) {
        __syncthreads();
        // stage Et: 64 rows x KC j, transposed (global reads coalesced along j)
        {
            int j = tid & 31, rb = tid >> 5;
#pragma unroll
            for (int k = 0; k < 8; k++) {
                int r = rb + k * 8;
                Et[j][r] = g_E[(size_t)(i0 + r) * NN + j0 + jc + j];
            }
        }
        // stage Fs: KC j x 64 u, scaled by colinv (512 float4, 2 per thread)
        {
#pragma unroll
            for (int k = 0; k < 2; k++) {
                int l = k * 256 + tid;
                int j = l >> 4, u4 = l & 15;
                float4 v = ((const float4*)(feature + (size_t)(j0 + jc + j) * UU))[u4];
                float cv = g_colinv[j0 + jc + j];
                v.x *= cv; v.y *= cv; v.z *= cv; v.w *= cv;
                ((float4*)&Fs[j][0])[u4] = v;
            }
        }
        __syncthreads();
#pragma unroll 8
        for (int jj = 0; jj < KC; jj++) {
            float4 e = *(const float4*)&Et[jj][ty * 4];
            float4 f = *(const float4*)&Fs[jj][tx * 4];
            acc[0][0] += e.x * f.x; acc[0][1] += e.x * f.y;
            acc[0][2] += e.x * f.z; acc[0][3] += e.x * f.w;
            acc[1][0] += e.y * f.x; acc[1][1] += e.y * f.y;
            acc[1][2] += e.y * f.z; acc[1][3] += e.y * f.w;
            acc[2][0] += e.z * f.x; acc[2][1] += e.z * f.y;
            acc[2][2] += e.z * f.z; acc[2][3] += e.z * f.w;
            acc[3][0] += e.w * f.x; acc[3][1] += e.w * f.y;
            acc[3][2] += e.w * f.z; acc[3][3] += e.w * f.w;
        }
    }
#pragma unroll
    for (int r = 0; r < 4; r++) {
        float4 v = make_float4(acc[r][0], acc[r][1], acc[r][2], acc[r][3]);
        *(float4*)&g_part[jt][i0 + ty * 4 + r][tx * 4] = v;
    }
}

// ---------------------------------------------------------------------------
// Kernel D2: proped = sum_jt part[jt]   (fixed order -> deterministic)
// ---------------------------------------------------------------------------
__global__ __launch_bounds__(256)
void reduce_kernel() {
    int idx = blockIdx.x * 256 + threadIdx.x;     // over NN*UU/4 = 32768 float4
    const float4* p0 = (const float4*)&g_part[0][0][0];
    const size_t stride = (size_t)NN * UU / 4;
    float4 s = p0[idx];
#pragma unroll
    for (int jt = 1; jt < JT; jt++) {
        float4 v = p0[jt * stride + idx];
        s.x += v.x; s.y += v.y; s.z += v.z; s.w += v.w;
    }
    ((float4*)g_proped)[idx] = s;
}

// ---------------------------------------------------------------------------
// Kernel E: prediction + losses, single block (256 thr x 8 rows),
// deterministic reduction.
// rank_loss = mean(relu(rr_i*rr_j*m_i*m_j)) = (P^2 + Ng^2)/N^2
//   with a_i = rr_i*m_i, P = sum(a_i>0), Ng = sum(a_i<0).
// ---------------------------------------------------------------------------
__global__ __launch_bounds__(256)
void loss_kernel(const float* __restrict__ feature,
                 const float* __restrict__ pred_w,
                 const float* __restrict__ pred_b,
                 const float* __restrict__ base_price,
                 const float* __restrict__ ground_truth,
                 const float* __restrict__ mask,
                 float* __restrict__ out, int out_size) {
    __shared__ float pw[2 * UU];
    __shared__ float s_sq[8], s_pos[8], s_neg[8];
    int tid = threadIdx.x;                // 256
    if (tid < 2 * UU) pw[tid] = pred_w[tid];
    __syncthreads();

    float pb = pred_b[0];
    float sq = 0.f, pos = 0.f, neg = 0.f;
    for (int k = 0; k < 8; k++) {
        int row = tid + k * 256;
        const float4* f = (const float4*)(feature + (size_t)row * UU);
        const float4* p = (const float4*)(g_proped + (size_t)row * UU);
        const float4* w0 = (const float4*)pw;
        const float4* w1 = (const float4*)(pw + UU);
        float d = 0.f;
#pragma unroll
        for (int r = 0; r < UU / 4; r++) {
            float4 v = f[r], w = w0[r];
            d += v.x * w.x + v.y * w.y + v.z * w.z + v.w * w.w;
        }
#pragma unroll
        for (int r = 0; r < UU / 4; r++) {
            float4 v = p[r], w = w1[r];
            d += v.x * w.x + v.y * w.y + v.z * w.z + v.w * w.w;
        }
        d += pb;
        float pred = (d >= 0.f) ? d : 0.2f * d;       // leaky_relu
        float bpv  = base_price[row];
        float rr   = (pred - bpv) / bpv;
        float diff = rr - ground_truth[row];
        sq += diff * diff;
        float a = rr * mask[row];
        pos += (a > 0.f) ? a : 0.f;
        neg += (a < 0.f) ? a : 0.f;
    }
#pragma unroll
    for (int o = 16; o; o >>= 1) {
        sq  += __shfl_down_sync(0xffffffffu, sq,  o);
        pos += __shfl_down_sync(0xffffffffu, pos, o);
        neg += __shfl_down_sync(0xffffffffu, neg, o);
    }
    if ((tid & 31) == 0) {
        s_sq[tid >> 5] = sq; s_pos[tid >> 5] = pos; s_neg[tid >> 5] = neg;
    }
    __syncthreads();
    if (tid == 0) {
        float tsq = 0.f, tp = 0.f, tn = 0.f;
#pragma unroll
        for (int k = 0; k < 8; k++) { tsq += s_sq[k]; tp += s_pos[k]; tn += s_neg[k]; }
        float reg  = tsq;
        float rank = (tp * tp + tn * tn) / ((float)NN * (float)NN);
        float loss = reg + 1.0f * rank;   // ALPHA = 1.0
        out[0] = loss;
        if (out_size > 1) out[1] = reg;
        if (out_size > 2) out[2] = rank;
    }
}

extern "C" void kernel_launch(void* const* d_in, const int* in_sizes, int n_in,
                              void* d_out, int out_size) {
    const float* feature      = (const float*)d_in[0];
    const float* relation     = (const float*)d_in[1];
    const float* rel_mask     = (const float*)d_in[2];
    const float* base_price   = (const float*)d_in[3];
    const float* ground_truth = (const float*)d_in[4];
    const float* mask         = (const float*)d_in[5];
    const float* rel_w        = (const float*)d_in[6];
    const float* rel_b        = (const float*)d_in[7];
    const float* head_w       = (const float*)d_in[8];
    const float* head_b       = (const float*)d_in[9];
    const float* tail_w       = (const float*)d_in[10];
    const float* tail_b       = (const float*)d_in[11];
    const float* pred_w       = (const float*)d_in[12];
    const float* pred_b       = (const float*)d_in[13];
    float* out = (float*)d_out;

    float* E;
    cudaGetSymbolAddress((void**)&E, g_E);

    head_tail_kernel<<<(NN + 255) / 256, 256>>>(feature, head_w, head_b, tail_w, tail_b);
    score_kernel<<<(size_t)NN * NN / 128, 256>>>(relation, rel_mask, rel_w, rel_b, E);
    colsum1_kernel<<<128, 256>>>();
    colsum2_kernel<<<NN / 256, 256>>>();
    agg_kernel<<<32 * JT, 256>>>(feature);
    reduce_kernel<<<NN * UU / 4 / 256, 256>>>();
    loss_kernel<<<1, 256>>>(feature, pred_w, pred_b, base_price, ground_truth,
                            mask, out, out_size);
}

// round 17
// speedup vs baseline: 1.4808x; 1.0020x over previous
#include <cuda_runtime.h>
#include <cstdint>

#define NN 2048
#define UU 64
#define RR 64
#define JT 32                // j-split tiles for agg
#define JC (NN / JT)         // 64 j per tile
#define KC 32                // j per smem stage
#define CS 64                // colsum partial slices

// ---- scratch (device globals; allocation is forbidden) ----
__device__ float g_E[(size_t)NN * NN];        // 16 MB: exp(score)
__device__ float g_head[NN];
__device__ float g_tail[NN];
__device__ float g_colpart[CS][NN];           // 512 KB colsum partials
__device__ float g_colinv[NN];                // 1 / sum_i E[i,j]
__device__ float g_part[JT][NN][UU];          // 16 MB agg partials
__device__ float g_proped[NN * UU];           // softmax(S,axis=0) @ feature

// ---------------------------------------------------------------------------
// Kernel A: head[n] = relu(feature[n]·head_w + head_b), tail likewise
// ---------------------------------------------------------------------------
__global__ __launch_bounds__(256)
void head_tail_kernel(const float* __restrict__ feature,
                      const float* __restrict__ head_w,
                      const float* __restrict__ head_b,
                      const float* __restrict__ tail_w,
                      const float* __restrict__ tail_b) {
    int n = blockIdx.x * blockDim.x + threadIdx.x;
    if (n >= NN) return;
    const float4* f  = (const float4*)(feature + (size_t)n * UU);
    const float4* hw = (const float4*)head_w;
    const float4* tw = (const float4*)tail_w;
    float h = 0.f, t = 0.f;
#pragma unroll
    for (int k = 0; k < UU / 4; k++) {
        float4 v = f[k], a = hw[k], b = tw[k];
        h += v.x * a.x + v.y * a.y + v.z * a.z + v.w * a.w;
        t += v.x * b.x + v.y * b.y + v.z * b.z + v.w * b.w;
    }
    g_head[n] = fmaxf(h + head_b[0], 0.f);
    g_tail[n] = fmaxf(t + tail_b[0], 0.f);
}

// ---------------------------------------------------------------------------
// Kernel B (dominant, DRAM-bound). 128 pairs/block: 8 front-batched LDG.128
// per thread (MLP=8, 32KB contiguous per block). relation/rel_mask via __ldcs
// (evict-first) so E stays L2-resident for the consumers.
// ---------------------------------------------------------------------------
__global__ __launch_bounds__(256)
void score_kernel(const float* __restrict__ relation,
                  const float* __restrict__ rel_mask,
                  const float* __restrict__ rel_w,
                  const float* __restrict__ rel_b,
                  float* __restrict__ E) {
    __shared__ float4 w4[16];
    __shared__ float ds[128];
    int tid = threadIdx.x;
    if (tid < 16) w4[tid] = ((const float4*)rel_w)[tid];
    __syncthreads();

    int lane = tid & 15;
    int g    = tid >> 4;                 // 16 groups of 16 lanes
    size_t pb = (size_t)blockIdx.x * 128;
    float4 w = w4[lane];

    const float4* rel4 = (const float4*)relation;

    float4 r[8];
#pragma unroll
    for (int k = 0; k < 8; k++)
        r[k] = __ldcs(&rel4[(pb + (size_t)k * 16 + g) * 16 + lane]);

#pragma unroll
    for (int k = 0; k < 8; k++) {
        float d = r[k].x * w.x + r[k].y * w.y + r[k].z * w.z + r[k].w * w.w;
#pragma unroll
        for (int o = 8; o; o >>= 1)
            d += __shfl_down_sync(0xffffffffu, d, o, 16);
        if (lane == 0) ds[k * 16 + g] = d;
    }
    __syncthreads();

    if (tid < 128) {
        size_t p = pb + tid;
        int i = (int)(p >> 11);
        int j = (int)(p & (NN - 1));
        float s = __ldcs(&rel_mask[p]) + g_head[i] + g_tail[j] +
                  fmaxf(ds[tid] + rel_b[0], 0.f);
        E[p] = __expf(s);                // masked (-1e9) underflows to 0
    }
}

// ---------------------------------------------------------------------------
// Kernel C1: row-coalesced partial column sums of E.
// Grid 128 = 4 col-tiles (512 cols) x 32 row-tiles (64 rows).
// Thread owns a float4 of columns; accumulates 32 rows with 4-way MLP.
// ---------------------------------------------------------------------------
__global__ __launch_bounds__(256)
void colsum1_kernel() {
    int tid = threadIdx.x;
    int cb = blockIdx.x & 3;          // col tile
    int rb = blockIdx.x >> 2;         // row tile 0..31
    int c4 = tid & 127;
    int rt = tid >> 7;                // 0..1
    int col = cb * 512 + c4 * 4;
    const float4* E4 = (const float4*)g_E;
    float4 a0 = make_float4(0, 0, 0, 0), a1 = a0, a2 = a0, a3 = a0;
    int base = rb * 64 + rt;
#pragma unroll 4
    for (int it = 0; it < 32; it += 4) {
        float4 v0 = E4[((size_t)(base + 2 * (it + 0)) * NN + col) >> 2];
        float4 v1 = E4[((size_t)(base + 2 * (it + 1)) * NN + col) >> 2];
        float4 v2 = E4[((size_t)(base + 2 * (it + 2)) * NN + col) >> 2];
        float4 v3 = E4[((size_t)(base + 2 * (it + 3)) * NN + col) >> 2];
        a0.x += v0.x; a0.y += v0.y; a0.z += v0.z; a0.w += v0.w;
        a1.x += v1.x; a1.y += v1.y; a1.z += v1.z; a1.w += v1.w;
        a2.x += v2.x; a2.y += v2.y; a2.z += v2.z; a2.w += v2.w;
        a3.x += v3.x; a3.y += v3.y; a3.z += v3.z; a3.w += v3.w;
    }
    float4 s = make_float4(a0.x + a1.x + a2.x + a3.x,
                           a0.y + a1.y + a2.y + a3.y,
                           a0.z + a1.z + a2.z + a3.z,
                           a0.w + a1.w + a2.w + a3.w);
    *(float4*)&g_colpart[rb * 2 + rt][col] = s;
}

// ---------------------------------------------------------------------------
// Kernel C2: colinv[j] = 1 / sum_k colpart[k][j]
// Grid 64 x 256: block owns 32 columns; 8 thread-groups each sum 8 slices;
// deterministic smem tree. Fixes the R16 straggler (grid-8, latency-bound).
// ---------------------------------------------------------------------------
__global__ __launch_bounds__(256)
void colsum2_kernel() {
    __shared__ float part[8][32];
    int c = threadIdx.x & 31;
    int g = threadIdx.x >> 5;            // 0..7
    int col = blockIdx.x * 32 + c;
    float s = 0.f;
#pragma unroll
    for (int k = 0; k < 8; k++)
        s += g_colpart[g * 8 + k][col];
    part[g][c] = s;
    __syncthreads();
    if (g == 0) {
        float t = 0.f;
#pragma unroll
        for (int k = 0; k < 8; k++) t += part[k][c];
        g_colinv[col] = 1.0f / t;
    }
}

// ---------------------------------------------------------------------------
// Kernel D: partial GEMM  part[jt] = E[:, jt-slice] @ (colinv ⊙ feature)[jt-slice]
// Grid 1024 = 32 row-tiles (64 rows) x 32 j-tiles (64 j). 256 thr as 16x16,
// each thread a 4x4 micro-tile: 2 LDS.128 + 16 FFMA per j-step.
// 5 blocks/SM (reg cap) -> occ 62.5%.
// ---------------------------------------------------------------------------
__global__ __launch_bounds__(256)
void agg_kernel(const float* __restrict__ feature) {
    __shared__ float Et[KC][68];      // E transposed [jj][row], pad 68
    __shared__ float Fs[KC][UU];      // colinv-scaled feature [jj][u]
    int tid = threadIdx.x;
    int tx = tid & 15;                // u block: u = tx*4..tx*4+3
    int ty = tid >> 4;                // row block: r = ty*4..ty*4+3
    int i0 = (blockIdx.x & 31) * 64;
    int jt = blockIdx.x >> 5;         // 0..31
    int j0 = jt * JC;

    float acc[4][4] = {};

#pragma unroll
    for (int jc = 0; jc < JC; jc += KC) {
        __syncthreads();
        // stage Et: 64 rows x KC j, transposed (global reads coalesced along j)
        {
            int j = tid & 31, rb = tid >> 5;
#pragma unroll
            for (int k = 0; k < 8; k++) {
                int r = rb + k * 8;
                Et[j][r] = g_E[(size_t)(i0 + r) * NN + j0 + jc + j];
            }
        }
        // stage Fs: KC j x 64 u, scaled by colinv (512 float4, 2 per thread)
        {
#pragma unroll
            for (int k = 0; k < 2; k++) {
                int l = k * 256 + tid;
                int j = l >> 4, u4 = l & 15;
                float4 v = ((const float4*)(feature + (size_t)(j0 + jc + j) * UU))[u4];
                float cv = g_colinv[j0 + jc + j];
                v.x *= cv; v.y *= cv; v.z *= cv; v.w *= cv;
                ((float4*)&Fs[j][0])[u4] = v;
            }
        }
        __syncthreads();
#pragma unroll 8
        for (int jj = 0; jj < KC; jj++) {
            float4 e = *(const float4*)&Et[jj][ty * 4];
            float4 f = *(const float4*)&Fs[jj][tx * 4];
            acc[0][0] += e.x * f.x; acc[0][1] += e.x * f.y;
            acc[0][2] += e.x * f.z; acc[0][3] += e.x * f.w;
            acc[1][0] += e.y * f.x; acc[1][1] += e.y * f.y;
            acc[1][2] += e.y * f.z; acc[1][3] += e.y * f.w;
            acc[2][0] += e.z * f.x; acc[2][1] += e.z * f.y;
            acc[2][2] += e.z * f.z; acc[2][3] += e.z * f.w;
            acc[3][0] += e.w * f.x; acc[3][1] += e.w * f.y;
            acc[3][2] += e.w * f.z; acc[3][3] += e.w * f.w;
        }
    }
#pragma unroll
    for (int r = 0; r < 4; r++) {
        float4 v = make_float4(acc[r][0], acc[r][1], acc[r][2], acc[r][3]);
        *(float4*)&g_part[jt][i0 + ty * 4 + r][tx * 4] = v;
    }
}

// ---------------------------------------------------------------------------
// Kernel D2: proped = sum_jt part[jt]   (fixed order -> deterministic)
// ---------------------------------------------------------------------------
__global__ __launch_bounds__(256)
void reduce_kernel() {
    int idx = blockIdx.x * 256 + threadIdx.x;     // over NN*UU/4 = 32768 float4
    const float4* p0 = (const float4*)&g_part[0][0][0];
    const size_t stride = (size_t)NN * UU / 4;
    float4 s = p0[idx];
#pragma unroll
    for (int jt = 1; jt < JT; jt++) {
        float4 v = p0[jt * stride + idx];
        s.x += v.x; s.y += v.y; s.z += v.z; s.w += v.w;
    }
    ((float4*)g_proped)[idx] = s;
}

// ---------------------------------------------------------------------------
// Kernel E: prediction + losses, single block (256 thr x 8 rows),
// deterministic reduction.
// rank_loss = mean(relu(rr_i*rr_j*m_i*m_j)) = (P^2 + Ng^2)/N^2
//   with a_i = rr_i*m_i, P = sum(a_i>0), Ng = sum(a_i<0).
// ---------------------------------------------------------------------------
__global__ __launch_bounds__(256)
void loss_kernel(const float* __restrict__ feature,
                 const float* __restrict__ pred_w,
                 const float* __restrict__ pred_b,
                 const float* __restrict__ base_price,
                 const float* __restrict__ ground_truth,
                 const float* __restrict__ mask,
                 float* __restrict__ out, int out_size) {
    __shared__ float pw[2 * UU];
    __shared__ float s_sq[8], s_pos[8], s_neg[8];
    int tid = threadIdx.x;                // 256
    if (tid < 2 * UU) pw[tid] = pred_w[tid];
    __syncthreads();

    float pb = pred_b[0];
    float sq = 0.f, pos = 0.f, neg = 0.f;
    for (int k = 0; k < 8; k++) {
        int row = tid + k * 256;
        const float4* f = (const float4*)(feature + (size_t)row * UU);
        const float4* p = (const float4*)(g_proped + (size_t)row * UU);
        const float4* w0 = (const float4*)pw;
        const float4* w1 = (const float4*)(pw + UU);
        float d = 0.f;
#pragma unroll
        for (int r = 0; r < UU / 4; r++) {
            float4 v = f[r], w = w0[r];
            d += v.x * w.x + v.y * w.y + v.z * w.z + v.w * w.w;
        }
#pragma unroll
        for (int r = 0; r < UU / 4; r++) {
            float4 v = p[r], w = w1[r];
            d += v.x * w.x + v.y * w.y + v.z * w.z + v.w * w.w;
        }
        d += pb;
        float pred = (d >= 0.f) ? d : 0.2f * d;       // leaky_relu
        float bpv  = base_price[row];
        float rr   = (pred - bpv) / bpv;
        float diff = rr - ground_truth[row];
        sq += diff * diff;
        float a = rr * mask[row];
        pos += (a > 0.f) ? a : 0.f;
        neg += (a < 0.f) ? a : 0.f;
    }
#pragma unroll
    for (int o = 16; o; o >>= 1) {
        sq  += __shfl_down_sync(0xffffffffu, sq,  o);
        pos += __shfl_down_sync(0xffffffffu, pos, o);
        neg += __shfl_down_sync(0xffffffffu, neg, o);
    }
    if ((tid & 31) == 0) {
        s_sq[tid >> 5] = sq; s_pos[tid >> 5] = pos; s_neg[tid >> 5] = neg;
    }
    __syncthreads();
    if (tid == 0) {
        float tsq = 0.f, tp = 0.f, tn = 0.f;
#pragma unroll
        for (int k = 0; k < 8; k++) { tsq += s_sq[k]; tp += s_pos[k]; tn += s_neg[k]; }
        float reg  = tsq;
        float rank = (tp * tp + tn * tn) / ((float)NN * (float)NN);
        float loss = reg + 1.0f * rank;   // ALPHA = 1.0
        out[0] = loss;
        if (out_size > 1) out[1] = reg;
        if (out_size > 2) out[2] = rank;
    }
}

extern "C" void kernel_launch(void* const* d_in, const int* in_sizes, int n_in,
                              void* d_out, int out_size) {
    const float* feature      = (const float*)d_in[0];
    const float* relation     = (const float*)d_in[1];
    const float* rel_mask     = (const float*)d_in[2];
    const float* base_price   = (const float*)d_in[3];
    const float* ground_truth = (const float*)d_in[4];
    const float* mask         = (const float*)d_in[5];
    const float* rel_w        = (const float*)d_in[6];
    const float* rel_b        = (const float*)d_in[7];
    const float* head_w       = (const float*)d_in[8];
    const float* head_b       = (const float*)d_in[9];
    const float* tail_w       = (const float*)d_in[10];
    const float* tail_b       = (const float*)d_in[11];
    const float* pred_w       = (const float*)d_in[12];
    const float* pred_b       = (const float*)d_in[13];
    float* out = (float*)d_out;

    float* E;
    cudaGetSymbolAddress((void**)&E, g_E);

    head_tail_kernel<<<(NN + 255) / 256, 256>>>(feature, head_w, head_b, tail_w, tail_b);
    score_kernel<<<(size_t)NN * NN / 128, 256>>>(relation, rel_mask, rel_w, rel_b, E);
    colsum1_kernel<<<128, 256>>>();
    colsum2_kernel<<<NN / 32, 256>>>();
    agg_kernel<<<32 * JT, 256>>>(feature);
    reduce_kernel<<<NN * UU / 4 / 256, 256>>>();
    loss_kernel<<<1, 256>>>(feature, pred_w, pred_b, base_price, ground_truth,
                            mask, out, out_size);
}